// round 10
// baseline (speedup 1.0000x reference)
#include <cuda_runtime.h>
#include <cuda_bf16.h>
#include <cstdint>

#define NMAX 100000
#define EMAX 1700000
#define Dd 100
#define KDATA 200
#define NP 104            // padded output cols (13 x n8)
#define KP 216            // smem k-stride (208 data+pad, conflict-free for ldmatrix)
#define NTHREADS 256
#define SCAN_B 1024

__device__ float g_agg[(size_t)NMAX * Dd];
__device__ float g_feat[(size_t)NMAX * Dd];
__device__ int   g_deg[NMAX];
__device__ int   g_off[NMAX + 1];
__device__ int   g_cur[NMAX];
__device__ int   g_csr[EMAX];
__device__ int   g_bsum[(NMAX + SCAN_B - 1) / SCAN_B];
__device__ __nv_bfloat16 g_Bhi[3][NP * KP];   // [set][n*KP + k], k-contiguous
__device__ __nv_bfloat16 g_Blo[3][NP * KP];

// ---------------- Weight prep (also clears deg: fused memset) ----------------
__global__ void prep_kernel(const float* __restrict__ Wsa, const float* __restrict__ Wsr,
                            const float* __restrict__ Wma, const float* __restrict__ Wmr,
                            const float* __restrict__ Wva, const float* __restrict__ Wvr,
                            int n)
{
    int i = blockIdx.x * blockDim.x + threadIdx.x;
    if (i < n) g_deg[i] = 0;
    if (i >= 3 * NP * KP) return;
    int s = i / (NP * KP);
    int rem = i - s * (NP * KP);
    int nIdx = rem / KP;
    int k = rem - nIdx * KP;
    const float* Wa = (s == 0) ? Wsa : (s == 1) ? Wma : Wva;
    const float* Wr = (s == 0) ? Wsr : (s == 1) ? Wmr : Wvr;
    float v = 0.f;
    if (nIdx < Dd && k < KDATA)
        v = (k < Dd) ? __ldg(Wa + k * Dd + nIdx) : __ldg(Wr + (k - Dd) * Dd + nIdx);
    __nv_bfloat16 h = __float2bfloat16(v);
    __nv_bfloat16 l = __float2bfloat16(v - __bfloat162float(h));
    g_Bhi[s][rem] = h;
    g_Blo[s][rem] = l;
}

// ---------------- CSR build ----------------
__global__ void hist_kernel(const int* __restrict__ dst, int* deg, int nE) {
    int e = blockIdx.x * blockDim.x + threadIdx.x;
    if (e < nE) atomicAdd(deg + __ldg(dst + e), 1);
}

__global__ void scanA_kernel(const int* __restrict__ deg, int* scanOut,
                             int* bsum, int n) {
    __shared__ int sm[SCAN_B];
    int i = blockIdx.x * SCAN_B + threadIdx.x;
    int v = (i < n) ? deg[i] : 0;
    sm[threadIdx.x] = v;
    __syncthreads();
    for (int o = 1; o < SCAN_B; o <<= 1) {
        int t = (threadIdx.x >= o) ? sm[threadIdx.x - o] : 0;
        __syncthreads();
        sm[threadIdx.x] += t;
        __syncthreads();
    }
    if (i < n) scanOut[i] = sm[threadIdx.x];
    if (threadIdx.x == SCAN_B - 1) bsum[blockIdx.x] = sm[SCAN_B - 1];
}

// Merged scanB+scanC: each block redundantly scans the (<=128) block sums with
// warp 0, then applies its exclusive prefix.
__global__ void scanBC_kernel(const int* __restrict__ scanIn,
                              const int* __restrict__ bsum,
                              const int* __restrict__ deg,
                              int* off, int* cur, int n, int nb) {
    __shared__ int spre[128];
    if (threadIdx.x < 32) {
        int lane = threadIdx.x;
        int carry = 0;
        for (int base = 0; base < nb; base += 32) {
            int i2 = base + lane;
            int orig = (i2 < nb) ? bsum[i2] : 0;
            int v = orig;
            #pragma unroll
            for (int o = 1; o < 32; o <<= 1) {
                int t = __shfl_up_sync(0xffffffffu, v, o);
                if (lane >= o) v += t;
            }
            if (i2 < 128) spre[i2] = carry + (v - orig);   // exclusive prefix
            carry += __shfl_sync(0xffffffffu, v, 31);
        }
    }
    __syncthreads();
    int i = blockIdx.x * SCAN_B + threadIdx.x;
    if (i < n) {
        int incl = scanIn[i] + spre[blockIdx.x];
        off[i + 1] = incl;
        cur[i] = incl - deg[i];
    }
    if (i == 0) off[0] = 0;
}

__global__ void scatter_kernel(const int* __restrict__ src,
                               const int* __restrict__ dst,
                               int* cur, int* csr, int nE) {
    int e = blockIdx.x * blockDim.x + threadIdx.x;
    if (e >= nE) return;
    int pos = atomicAdd(cur + __ldg(dst + e), 1);
    csr[pos] = __ldg(src + e);
}

// ---------------- Gather aggregation: mean of neighbor rows, MLP=4 ----------------
__global__ void gather_kernel(const float* __restrict__ xin,
                              const int* __restrict__ csr,
                              const int* __restrict__ off,
                              float* __restrict__ aggOut, int n)
{
    int node = blockIdx.x * 8 + (threadIdx.x >> 5);
    int lane = threadIdx.x & 31;
    if (node >= n) return;
    int s0 = __ldg(off + node), s1 = __ldg(off + node + 1);

    float4 a0 = make_float4(0.f, 0.f, 0.f, 0.f);
    float4 a1 = a0, a2 = a0, a3 = a0;
    int j = s0;
    for (; j + 4 <= s1; j += 4) {
        int i0 = __ldg(csr + j);
        int i1 = __ldg(csr + j + 1);
        int i2 = __ldg(csr + j + 2);
        int i3 = __ldg(csr + j + 3);
        if (lane < 25) {
            float4 v0 = __ldg(reinterpret_cast<const float4*>(xin + (size_t)i0 * Dd) + lane);
            float4 v1 = __ldg(reinterpret_cast<const float4*>(xin + (size_t)i1 * Dd) + lane);
            float4 v2 = __ldg(reinterpret_cast<const float4*>(xin + (size_t)i2 * Dd) + lane);
            float4 v3 = __ldg(reinterpret_cast<const float4*>(xin + (size_t)i3 * Dd) + lane);
            a0.x += v0.x; a0.y += v0.y; a0.z += v0.z; a0.w += v0.w;
            a1.x += v1.x; a1.y += v1.y; a1.z += v1.z; a1.w += v1.w;
            a2.x += v2.x; a2.y += v2.y; a2.z += v2.z; a2.w += v2.w;
            a3.x += v3.x; a3.y += v3.y; a3.z += v3.z; a3.w += v3.w;
        }
    }
    for (; j < s1; j++) {
        int i0 = __ldg(csr + j);
        if (lane < 25) {
            float4 v0 = __ldg(reinterpret_cast<const float4*>(xin + (size_t)i0 * Dd) + lane);
            a0.x += v0.x; a0.y += v0.y; a0.z += v0.z; a0.w += v0.w;
        }
    }
    if (lane < 25) {
        float4 acc;
        acc.x = (a0.x + a1.x) + (a2.x + a3.x);
        acc.y = (a0.y + a1.y) + (a2.y + a3.y);
        acc.z = (a0.z + a1.z) + (a2.z + a3.z);
        acc.w = (a0.w + a1.w) + (a2.w + a3.w);
        float inv = (s1 > s0) ? 1.0f / (float)(s1 - s0) : 0.f;
        acc.x *= inv; acc.y *= inv; acc.z *= inv; acc.w *= inv;
        reinterpret_cast<float4*>(aggOut + (size_t)node * Dd)[lane] = acc;
    }
}

// ---------------- Tensor-core layer (mma.sync bf16 3-term split) ----------------
__global__ void __launch_bounds__(NTHREADS)
layer_mma(const float* __restrict__ agg, const float* __restrict__ root,
          const __nv_bfloat16* __restrict__ Bhi0, const __nv_bfloat16* __restrict__ Blo0,
          const float* __restrict__ bias0,
          const __nv_bfloat16* __restrict__ Bhi1, const __nv_bfloat16* __restrict__ Blo1,
          const float* __restrict__ bias1,
          float* __restrict__ out, int n, int doRelu)
{
    extern __shared__ char smraw[];
    float* sbias = reinterpret_cast<float*>(smraw);                    // 104 floats
    __nv_bfloat16* sA = reinterpret_cast<__nv_bfloat16*>(smraw + 512);
    __nv_bfloat16* Ahi = sA;
    __nv_bfloat16* Alo = Ahi + 128 * KP;
    __nv_bfloat16* Bhi = Alo + 128 * KP;
    __nv_bfloat16* Blo = Bhi + NP * KP;

    const __nv_bfloat16* gBhi = blockIdx.y ? Bhi1 : Bhi0;
    const __nv_bfloat16* gBlo = blockIdx.y ? Blo1 : Blo0;
    const float* gb = blockIdx.y ? bias1 : bias0;
    out += (size_t)blockIdx.y * n * Dd;

    const int tid = threadIdx.x;
    const int base = blockIdx.x * 128;

    {
        const float4* sh = reinterpret_cast<const float4*>(gBhi);
        const float4* sl = reinterpret_cast<const float4*>(gBlo);
        float4* dh = reinterpret_cast<float4*>(Bhi);
        float4* dl = reinterpret_cast<float4*>(Blo);
        for (int i = tid; i < (NP * KP * 2) / 16; i += NTHREADS) {
            dh[i] = __ldg(sh + i);
            dl[i] = __ldg(sl + i);
        }
    }
    if (tid < NP) sbias[tid] = (tid < Dd) ? __ldg(gb + tid) : 0.f;

    for (int idx = tid; idx < 128 * 50; idx += NTHREADS) {
        int r = idx / 50, q = idx - r * 50;
        int node = base + r;
        float4 v = make_float4(0.f, 0.f, 0.f, 0.f);
        if (node < n)
            v = (q < 25) ? __ldg(reinterpret_cast<const float4*>(
                                 agg + (size_t)node * Dd) + q)
                         : __ldg(reinterpret_cast<const float4*>(
                                 root + (size_t)node * Dd) + (q - 25));
        int kb = (q < 25) ? q * 4 : 100 + (q - 25) * 4;
        __nv_bfloat162 h01 = __floats2bfloat162_rn(v.x, v.y);
        __nv_bfloat162 h23 = __floats2bfloat162_rn(v.z, v.w);
        float2 f01 = __bfloat1622float2(h01);
        float2 f23 = __bfloat1622float2(h23);
        __nv_bfloat162 l01 = __floats2bfloat162_rn(v.x - f01.x, v.y - f01.y);
        __nv_bfloat162 l23 = __floats2bfloat162_rn(v.z - f23.x, v.w - f23.y);
        uint32_t* dh = reinterpret_cast<uint32_t*>(Ahi + r * KP + kb);
        uint32_t* dl = reinterpret_cast<uint32_t*>(Alo + r * KP + kb);
        dh[0] = *reinterpret_cast<uint32_t*>(&h01);
        dh[1] = *reinterpret_cast<uint32_t*>(&h23);
        dl[0] = *reinterpret_cast<uint32_t*>(&l01);
        dl[1] = *reinterpret_cast<uint32_t*>(&l23);
    }
    for (int i = tid; i < 128 * 4; i += NTHREADS) {
        int r = i >> 2, c = i & 3;
        reinterpret_cast<uint32_t*>(Ahi)[r * (KP / 2) + 100 + c] = 0u;
        reinterpret_cast<uint32_t*>(Alo)[r * (KP / 2) + 100 + c] = 0u;
    }
    __syncthreads();

    const int lane = tid & 31;
    const int m0 = (tid >> 5) * 16;

    float acc[13][4];
    #pragma unroll
    for (int t = 0; t < 13; t++)
        acc[t][0] = acc[t][1] = acc[t][2] = acc[t][3] = 0.f;

    const int arow = m0 + (lane & 15);
    const int akoff = (lane >> 4) << 3;
    const int brow = lane & 7;
    const int bkoff = ((lane >> 3) & 1) << 3;

    #pragma unroll 1
    for (int ks = 0; ks < 13; ks++) {
        int k0 = ks * 16;
        uint32_t ah[4], al[4];
        {
            uint32_t addr = (uint32_t)__cvta_generic_to_shared(
                Ahi + arow * KP + k0 + akoff);
            asm volatile(
                "ldmatrix.sync.aligned.m8n8.x4.shared.b16 {%0,%1,%2,%3}, [%4];"
                : "=r"(ah[0]), "=r"(ah[1]), "=r"(ah[2]), "=r"(ah[3]) : "r"(addr));
        }
        {
            uint32_t addr = (uint32_t)__cvta_generic_to_shared(
                Alo + arow * KP + k0 + akoff);
            asm volatile(
                "ldmatrix.sync.aligned.m8n8.x4.shared.b16 {%0,%1,%2,%3}, [%4];"
                : "=r"(al[0]), "=r"(al[1]), "=r"(al[2]), "=r"(al[3]) : "r"(addr));
        }

        uint32_t bf[13][2];
        #pragma unroll
        for (int nt = 0; nt < 13; nt++) {
            uint32_t baddr = (uint32_t)__cvta_generic_to_shared(
                Bhi + (nt * 8 + brow) * KP + k0 + bkoff);
            asm volatile(
                "ldmatrix.sync.aligned.m8n8.x2.shared.b16 {%0,%1}, [%2];"
                : "=r"(bf[nt][0]), "=r"(bf[nt][1]) : "r"(baddr));
        }
        #pragma unroll
        for (int nt = 0; nt < 13; nt++)
            asm volatile(
                "mma.sync.aligned.m16n8k16.row.col.f32.bf16.bf16.f32 "
                "{%0,%1,%2,%3}, {%4,%5,%6,%7}, {%8,%9}, {%0,%1,%2,%3};"
                : "+f"(acc[nt][0]), "+f"(acc[nt][1]),
                  "+f"(acc[nt][2]), "+f"(acc[nt][3])
                : "r"(ah[0]), "r"(ah[1]), "r"(ah[2]), "r"(ah[3]),
                  "r"(bf[nt][0]), "r"(bf[nt][1]));
        #pragma unroll
        for (int nt = 0; nt < 13; nt++)
            asm volatile(
                "mma.sync.aligned.m16n8k16.row.col.f32.bf16.bf16.f32 "
                "{%0,%1,%2,%3}, {%4,%5,%6,%7}, {%8,%9}, {%0,%1,%2,%3};"
                : "+f"(acc[nt][0]), "+f"(acc[nt][1]),
                  "+f"(acc[nt][2]), "+f"(acc[nt][3])
                : "r"(al[0]), "r"(al[1]), "r"(al[2]), "r"(al[3]),
                  "r"(bf[nt][0]), "r"(bf[nt][1]));
        #pragma unroll
        for (int nt = 0; nt < 13; nt++) {
            uint32_t baddr = (uint32_t)__cvta_generic_to_shared(
                Blo + (nt * 8 + brow) * KP + k0 + bkoff);
            asm volatile(
                "ldmatrix.sync.aligned.m8n8.x2.shared.b16 {%0,%1}, [%2];"
                : "=r"(bf[nt][0]), "=r"(bf[nt][1]) : "r"(baddr));
        }
        #pragma unroll
        for (int nt = 0; nt < 13; nt++)
            asm volatile(
                "mma.sync.aligned.m16n8k16.row.col.f32.bf16.bf16.f32 "
                "{%0,%1,%2,%3}, {%4,%5,%6,%7}, {%8,%9}, {%0,%1,%2,%3};"
                : "+f"(acc[nt][0]), "+f"(acc[nt][1]),
                  "+f"(acc[nt][2]), "+f"(acc[nt][3])
                : "r"(ah[0]), "r"(ah[1]), "r"(ah[2]), "r"(ah[3]),
                  "r"(bf[nt][0]), "r"(bf[nt][1]));
    }

    int row0 = base + m0 + (lane >> 2);
    int row1 = row0 + 8;
    #pragma unroll
    for (int nt = 0; nt < 13; nt++) {
        int col0 = nt * 8 + ((lane & 3) << 1);
        if (col0 >= Dd) continue;
        float bv0 = sbias[col0], bv1 = sbias[col0 + 1];
        float v00 = acc[nt][0] + bv0, v01 = acc[nt][1] + bv1;
        float v10 = acc[nt][2] + bv0, v11 = acc[nt][3] + bv1;
        if (doRelu) {
            v00 = fmaxf(v00, 0.f); v01 = fmaxf(v01, 0.f);
            v10 = fmaxf(v10, 0.f); v11 = fmaxf(v11, 0.f);
        }
        if (row0 < n)
            *reinterpret_cast<float2*>(out + (size_t)row0 * Dd + col0) =
                make_float2(v00, v01);
        if (row1 < n)
            *reinterpret_cast<float2*>(out + (size_t)row1 * Dd + col0) =
                make_float2(v10, v11);
    }
}

extern "C" void kernel_launch(void* const* d_in, const int* in_sizes, int n_in,
                              void* d_out, int out_size)
{
    const float* x   = (const float*)d_in[0];
    const int*   ei  = (const int*)d_in[1];
    const float* Wsa = (const float*)d_in[3];
    const float* Wsr = (const float*)d_in[4];
    const float* bs_ = (const float*)d_in[5];
    const float* Wma = (const float*)d_in[6];
    const float* Wmr = (const float*)d_in[7];
    const float* bm  = (const float*)d_in[8];
    const float* Wva = (const float*)d_in[9];
    const float* Wvr = (const float*)d_in[10];
    const float* bv  = (const float*)d_in[11];

    int n  = in_sizes[0] / Dd;
    int nE = in_sizes[1] / 2;
    const int* src  = ei;
    const int* dstp = ei + nE;

    float *agg, *feat;
    int *deg, *off, *cur, *csr, *bsum;
    __nv_bfloat16 *bhiBase, *bloBase;
    cudaGetSymbolAddress((void**)&agg,  g_agg);
    cudaGetSymbolAddress((void**)&feat, g_feat);
    cudaGetSymbolAddress((void**)&deg,  g_deg);
    cudaGetSymbolAddress((void**)&off,  g_off);
    cudaGetSymbolAddress((void**)&cur,  g_cur);
    cudaGetSymbolAddress((void**)&csr,  g_csr);
    cudaGetSymbolAddress((void**)&bsum, g_bsum);
    cudaGetSymbolAddress((void**)&bhiBase, g_Bhi);
    cudaGetSymbolAddress((void**)&bloBase, g_Blo);

    size_t smem = 512 + (size_t)(2 * 128 + 2 * NP) * KP * sizeof(__nv_bfloat16);
    static bool attrSet = false;
    if (!attrSet) {
        cudaFuncSetAttribute(layer_mma,
                             cudaFuncAttributeMaxDynamicSharedMemorySize, (int)smem);
        attrSet = true;
    }

    // (0) Weight prep + deg clear
    int prepThreads = (3 * NP * KP > n) ? 3 * NP * KP : n;
    prep_kernel<<<(prepThreads + 255) / 256, 256>>>(Wsa, Wsr, Wma, Wmr, Wva, Wvr, n);

    // (1-4) CSR build
    int nb = (n + SCAN_B - 1) / SCAN_B;
    hist_kernel<<<(nE + 255) / 256, 256>>>(dstp, deg, nE);
    scanA_kernel<<<nb, SCAN_B>>>(deg, cur, bsum, n);
    scanBC_kernel<<<nb, SCAN_B>>>(cur, bsum, deg, off, cur, n, nb);
    scatter_kernel<<<(nE + 255) / 256, 256>>>(src, dstp, cur, csr, nE);

    // (5) gather 1 -- ncu -s 5 captures this launch
    int gatherBlocks = (n + 7) / 8;
    gather_kernel<<<gatherBlocks, 256>>>(x, csr, off, agg, n);

    // (6) layer 1
    int rowBlocks = (n + 127) / 128;
    layer_mma<<<dim3(rowBlocks, 1), NTHREADS, smem>>>(
        agg, x, bhiBase, bloBase, bs_,
        bhiBase, bloBase, bs_, feat, n, 1);

    // (7) gather 2, (8) layers 2+3 fused
    gather_kernel<<<gatherBlocks, 256>>>(feat, csr, off, agg, n);

    float* outp = (float*)d_out;
    layer_mma<<<dim3(rowBlocks, 2), NTHREADS, smem>>>(
        agg, feat,
        bhiBase + (size_t)1 * NP * KP, bloBase + (size_t)1 * NP * KP, bm,
        bhiBase + (size_t)2 * NP * KP, bloBase + (size_t)2 * NP * KP, bv,
        outp, n, 0);
}

// round 14
// speedup vs baseline: 1.3132x; 1.3132x over previous
#include <cuda_runtime.h>
#include <cuda_bf16.h>
#include <cstdint>

#define NMAX 100000
#define EMAX 1700000
#define Dd 100
#define KDATA 200
#define NP 104            // padded output cols (13 x n8)
#define KP 216            // smem k-stride (conflict-free for ldmatrix)
#define MROWS 64          // rows per CTA
#define NTHREADS 256
#define SCAN_B 1024

__device__ float g_agg[(size_t)NMAX * Dd];
__device__ float g_feat[(size_t)NMAX * Dd];
__device__ int   g_deg[NMAX];
__device__ int   g_off[NMAX + 1];
__device__ int   g_cur[NMAX];
__device__ int   g_csr[EMAX];
__device__ int   g_bsum[(NMAX + SCAN_B - 1) / SCAN_B];
__device__ __nv_bfloat16 g_Bhi[3][NP * KP];   // [set][n*KP + k], k-contiguous
__device__ __nv_bfloat16 g_Blo[3][NP * KP];

// ---------------- CSR build: histogram -> scan -> scatter ----------------

__global__ void hist_kernel(const int* __restrict__ dst, int* deg, int nE) {
    int e = blockIdx.x * blockDim.x + threadIdx.x;
    if (e < nE) atomicAdd(deg + __ldg(dst + e), 1);
}

__global__ void scanA_kernel(const int* __restrict__ deg, int* scanOut,
                             int* bsum, int n) {
    __shared__ int sm[SCAN_B];
    int i = blockIdx.x * SCAN_B + threadIdx.x;
    int v = (i < n) ? deg[i] : 0;
    sm[threadIdx.x] = v;
    __syncthreads();
    for (int o = 1; o < SCAN_B; o <<= 1) {
        int t = (threadIdx.x >= o) ? sm[threadIdx.x - o] : 0;
        __syncthreads();
        sm[threadIdx.x] += t;
        __syncthreads();
    }
    if (i < n) scanOut[i] = sm[threadIdx.x];
    if (threadIdx.x == SCAN_B - 1) bsum[blockIdx.x] = sm[SCAN_B - 1];
}

__global__ void scanB_kernel(int* bsum, int nb) {
    int lane = threadIdx.x;
    int carry = 0;
    for (int base = 0; base < nb; base += 32) {
        int i = base + lane;
        int orig = (i < nb) ? bsum[i] : 0;
        int v = orig;
        #pragma unroll
        for (int o = 1; o < 32; o <<= 1) {
            int t = __shfl_up_sync(0xffffffffu, v, o);
            if (lane >= o) v += t;
        }
        if (i < nb) bsum[i] = carry + (v - orig);
        carry += __shfl_sync(0xffffffffu, v, 31);
    }
}

__global__ void scanC_kernel(const int* __restrict__ scanIn,
                             const int* __restrict__ bsum,
                             const int* __restrict__ deg,
                             int* off, int* cur, int n) {
    int i = blockIdx.x * SCAN_B + threadIdx.x;
    if (i < n) {
        int incl = scanIn[i] + bsum[blockIdx.x];
        off[i + 1] = incl;
        cur[i] = incl - deg[i];
    }
    if (i == 0) off[0] = 0;
}

__global__ void scatter_kernel(const int* __restrict__ src,
                               const int* __restrict__ dst,
                               int* cur, int* csr, int nE) {
    int e = blockIdx.x * blockDim.x + threadIdx.x;
    if (e >= nE) return;
    int pos = atomicAdd(cur + __ldg(dst + e), 1);
    csr[pos] = __ldg(src + e);
}

// ---------------- Gather aggregation: mean of neighbor rows ----------------

__global__ void gather_kernel(const float* __restrict__ xin,
                              const int* __restrict__ csr,
                              const int* __restrict__ off,
                              float* __restrict__ aggOut, int n)
{
    int node = blockIdx.x * 8 + (threadIdx.x >> 5);
    int lane = threadIdx.x & 31;
    if (node >= n) return;
    int s0 = __ldg(off + node), s1 = __ldg(off + node + 1);
    float4 acc = make_float4(0.f, 0.f, 0.f, 0.f);
    int j = s0;
    int idx = (j < s1) ? __ldg(csr + j) : 0;
    while (j < s1) {
        int nidx = (j + 1 < s1) ? __ldg(csr + j + 1) : 0;
        if (lane < 25) {
            float4 v = __ldg(reinterpret_cast<const float4*>(
                    xin + (size_t)idx * Dd) + lane);
            acc.x += v.x; acc.y += v.y; acc.z += v.z; acc.w += v.w;
        }
        idx = nidx;
        j++;
    }
    if (lane < 25) {
        float inv = (s1 > s0) ? 1.0f / (float)(s1 - s0) : 0.f;
        acc.x *= inv; acc.y *= inv; acc.z *= inv; acc.w *= inv;
        reinterpret_cast<float4*>(aggOut + (size_t)node * Dd)[lane] = acc;
    }
}

// ---------------- Weight prep: fp32 W -> padded, transposed bf16 hi/lo ----------------
__global__ void prep_kernel(const float* __restrict__ Wsa, const float* __restrict__ Wsr,
                            const float* __restrict__ Wma, const float* __restrict__ Wmr,
                            const float* __restrict__ Wva, const float* __restrict__ Wvr)
{
    int i = blockIdx.x * blockDim.x + threadIdx.x;
    if (i >= 3 * NP * KP) return;
    int s = i / (NP * KP);
    int rem = i - s * (NP * KP);
    int nIdx = rem / KP;
    int k = rem - nIdx * KP;
    const float* Wa = (s == 0) ? Wsa : (s == 1) ? Wma : Wva;
    const float* Wr = (s == 0) ? Wsr : (s == 1) ? Wmr : Wvr;
    float v = 0.f;
    if (nIdx < Dd && k < KDATA)
        v = (k < Dd) ? __ldg(Wa + k * Dd + nIdx) : __ldg(Wr + (k - Dd) * Dd + nIdx);
    __nv_bfloat16 h = __float2bfloat16(v);
    __nv_bfloat16 l = __float2bfloat16(v - __bfloat162float(h));
    g_Bhi[s][rem] = h;
    g_Blo[s][rem] = l;
}

// ---------------- MMA pass helper ----------------
// One warp computes rows [arow-tile] x n-tiles [NTBASE, NTBASE+NTC).
template<bool DOLO, int NTBASE, int NTC>
__device__ __forceinline__ void mma_pass(
    const __nv_bfloat16* __restrict__ Ahi, const __nv_bfloat16* __restrict__ Alo,
    const __nv_bfloat16* __restrict__ Bbuf, float (*acc)[4],
    int arow, int akoff, int brow, int bkoff)
{
    #pragma unroll 1
    for (int ks = 0; ks < 13; ks++) {
        int k0 = ks * 16;
        uint32_t ah[4], al[4];
        {
            uint32_t addr = (uint32_t)__cvta_generic_to_shared(
                Ahi + arow * KP + k0 + akoff);
            asm volatile(
                "ldmatrix.sync.aligned.m8n8.x4.shared.b16 {%0,%1,%2,%3}, [%4];"
                : "=r"(ah[0]), "=r"(ah[1]), "=r"(ah[2]), "=r"(ah[3]) : "r"(addr));
        }
        if (DOLO) {
            uint32_t addr = (uint32_t)__cvta_generic_to_shared(
                Alo + arow * KP + k0 + akoff);
            asm volatile(
                "ldmatrix.sync.aligned.m8n8.x4.shared.b16 {%0,%1,%2,%3}, [%4];"
                : "=r"(al[0]), "=r"(al[1]), "=r"(al[2]), "=r"(al[3]) : "r"(addr));
        }
        uint32_t bf[NTC][2];
        #pragma unroll
        for (int t = 0; t < NTC; t++) {
            uint32_t baddr = (uint32_t)__cvta_generic_to_shared(
                Bbuf + ((NTBASE + t) * 8 + brow) * KP + k0 + bkoff);
            asm volatile(
                "ldmatrix.sync.aligned.m8n8.x2.shared.b16 {%0,%1}, [%2];"
                : "=r"(bf[t][0]), "=r"(bf[t][1]) : "r"(baddr));
        }
        #pragma unroll
        for (int t = 0; t < NTC; t++)
            asm volatile(
                "mma.sync.aligned.m16n8k16.row.col.f32.bf16.bf16.f32 "
                "{%0,%1,%2,%3}, {%4,%5,%6,%7}, {%8,%9}, {%0,%1,%2,%3};"
                : "+f"(acc[t][0]), "+f"(acc[t][1]), "+f"(acc[t][2]), "+f"(acc[t][3])
                : "r"(ah[0]), "r"(ah[1]), "r"(ah[2]), "r"(ah[3]),
                  "r"(bf[t][0]), "r"(bf[t][1]));
        if (DOLO) {
            #pragma unroll
            for (int t = 0; t < NTC; t++)
                asm volatile(
                    "mma.sync.aligned.m16n8k16.row.col.f32.bf16.bf16.f32 "
                    "{%0,%1,%2,%3}, {%4,%5,%6,%7}, {%8,%9}, {%0,%1,%2,%3};"
                    : "+f"(acc[t][0]), "+f"(acc[t][1]), "+f"(acc[t][2]), "+f"(acc[t][3])
                    : "r"(al[0]), "r"(al[1]), "r"(al[2]), "r"(al[3]),
                      "r"(bf[t][0]), "r"(bf[t][1]));
        }
    }
}

// ---------------- Tensor-core layer: 64-row CTAs, 2 CTAs/SM, B restaged ----------------
// Warps: (wid&3) = row tile (16 rows), (wid>>2) = col group (nt 0..6 / 7..12).
__global__ void __launch_bounds__(NTHREADS, 2)
layer_mma(const float* __restrict__ agg, const float* __restrict__ root,
          const __nv_bfloat16* __restrict__ Bhi0, const __nv_bfloat16* __restrict__ Blo0,
          const float* __restrict__ bias0,
          const __nv_bfloat16* __restrict__ Bhi1, const __nv_bfloat16* __restrict__ Blo1,
          const float* __restrict__ bias1,
          float* __restrict__ out, int n, int doRelu)
{
    extern __shared__ char smraw[];
    float* sbias = reinterpret_cast<float*>(smraw);                    // 128 floats
    __nv_bfloat16* Ahi = reinterpret_cast<__nv_bfloat16*>(smraw + 512);
    __nv_bfloat16* Alo = Ahi + MROWS * KP;
    __nv_bfloat16* Bbuf = Alo + MROWS * KP;

    const __nv_bfloat16* gBhi = blockIdx.y ? Bhi1 : Bhi0;
    const __nv_bfloat16* gBlo = blockIdx.y ? Blo1 : Blo0;
    const float* gb = blockIdx.y ? bias1 : bias0;
    out += (size_t)blockIdx.y * n * Dd;

    const int tid = threadIdx.x;
    const int base = blockIdx.x * MROWS;

    // Stage Bhi
    {
        const float4* sh = reinterpret_cast<const float4*>(gBhi);
        float4* dh = reinterpret_cast<float4*>(Bbuf);
        for (int i = tid; i < (NP * KP) / 8; i += NTHREADS) dh[i] = __ldg(sh + i);
    }
    if (tid < NP) sbias[tid] = (tid < Dd) ? __ldg(gb + tid) : 0.f;

    // Stage A hi/lo: MROWS rows x 50 float4 chunks.
    for (int idx = tid; idx < MROWS * 50; idx += NTHREADS) {
        int r = idx / 50, q = idx - r * 50;
        int node = base + r;
        float4 v = make_float4(0.f, 0.f, 0.f, 0.f);
        if (node < n)
            v = (q < 25) ? __ldg(reinterpret_cast<const float4*>(
                                 agg + (size_t)node * Dd) + q)
                         : __ldg(reinterpret_cast<const float4*>(
                                 root + (size_t)node * Dd) + (q - 25));
        int kb = (q < 25) ? q * 4 : 100 + (q - 25) * 4;
        __nv_bfloat162 h01 = __floats2bfloat162_rn(v.x, v.y);
        __nv_bfloat162 h23 = __floats2bfloat162_rn(v.z, v.w);
        float2 f01 = __bfloat1622float2(h01);
        float2 f23 = __bfloat1622float2(h23);
        __nv_bfloat162 l01 = __floats2bfloat162_rn(v.x - f01.x, v.y - f01.y);
        __nv_bfloat162 l23 = __floats2bfloat162_rn(v.z - f23.x, v.w - f23.y);
        uint32_t* dh = reinterpret_cast<uint32_t*>(Ahi + r * KP + kb);
        uint32_t* dl = reinterpret_cast<uint32_t*>(Alo + r * KP + kb);
        dh[0] = *reinterpret_cast<uint32_t*>(&h01);
        dh[1] = *reinterpret_cast<uint32_t*>(&h23);
        dl[0] = *reinterpret_cast<uint32_t*>(&l01);
        dl[1] = *reinterpret_cast<uint32_t*>(&l23);
    }
    // Zero A pad cols k=200..207.
    for (int i = tid; i < MROWS * 4; i += NTHREADS) {
        int r = i >> 2, c = i & 3;
        reinterpret_cast<uint32_t*>(Ahi)[r * (KP / 2) + 100 + c] = 0u;
        reinterpret_cast<uint32_t*>(Alo)[r * (KP / 2) + 100 + c] = 0u;
    }
    __syncthreads();

    const int lane = tid & 31;
    const int wid = tid >> 5;
    const int rowTile = wid & 3;
    const int colGrp = wid >> 2;

    const int arow = rowTile * 16 + (lane & 15);
    const int akoff = (lane >> 4) << 3;
    const int brow = lane & 7;
    const int bkoff = ((lane >> 3) & 1) << 3;

    float acc[7][4];
    #pragma unroll
    for (int t = 0; t < 7; t++)
        acc[t][0] = acc[t][1] = acc[t][2] = acc[t][3] = 0.f;

    // Phase 1: Ahi*Bhi + Alo*Bhi
    if (colGrp == 0)
        mma_pass<true, 0, 7>(Ahi, Alo, Bbuf, acc, arow, akoff, brow, bkoff);
    else
        mma_pass<true, 7, 6>(Ahi, Alo, Bbuf, acc, arow, akoff, brow, bkoff);

    // Restage Blo over the B buffer (mma.sync is warp-synchronous; barrier fences it)
    __syncthreads();
    {
        const float4* sl = reinterpret_cast<const float4*>(gBlo);
        float4* dh = reinterpret_cast<float4*>(Bbuf);
        for (int i = tid; i < (NP * KP) / 8; i += NTHREADS) dh[i] = __ldg(sl + i);
    }
    __syncthreads();

    // Phase 2: Ahi*Blo
    if (colGrp == 0)
        mma_pass<false, 0, 7>(Ahi, Alo, Bbuf, acc, arow, akoff, brow, bkoff);
    else
        mma_pass<false, 7, 6>(Ahi, Alo, Bbuf, acc, arow, akoff, brow, bkoff);

    // Epilogue: bias (+ReLU), store.
    const int ntBase = colGrp ? 7 : 0;
    const int ntCnt = colGrp ? 6 : 7;
    int row0 = base + rowTile * 16 + (lane >> 2);
    int row1 = row0 + 8;
    #pragma unroll
    for (int t = 0; t < 7; t++) {
        if (t >= ntCnt) break;
        int col0 = (ntBase + t) * 8 + ((lane & 3) << 1);
        if (col0 >= Dd) continue;
        float bv0 = sbias[col0], bv1 = sbias[col0 + 1];
        float v00 = acc[t][0] + bv0, v01 = acc[t][1] + bv1;
        float v10 = acc[t][2] + bv0, v11 = acc[t][3] + bv1;
        if (doRelu) {
            v00 = fmaxf(v00, 0.f); v01 = fmaxf(v01, 0.f);
            v10 = fmaxf(v10, 0.f); v11 = fmaxf(v11, 0.f);
        }
        if (row0 < n)
            *reinterpret_cast<float2*>(out + (size_t)row0 * Dd + col0) =
                make_float2(v00, v01);
        if (row1 < n)
            *reinterpret_cast<float2*>(out + (size_t)row1 * Dd + col0) =
                make_float2(v10, v11);
    }
}

extern "C" void kernel_launch(void* const* d_in, const int* in_sizes, int n_in,
                              void* d_out, int out_size)
{
    const float* x   = (const float*)d_in[0];
    const int*   ei  = (const int*)d_in[1];
    const float* Wsa = (const float*)d_in[3];
    const float* Wsr = (const float*)d_in[4];
    const float* bs_ = (const float*)d_in[5];
    const float* Wma = (const float*)d_in[6];
    const float* Wmr = (const float*)d_in[7];
    const float* bm  = (const float*)d_in[8];
    const float* Wva = (const float*)d_in[9];
    const float* Wvr = (const float*)d_in[10];
    const float* bv  = (const float*)d_in[11];

    int n  = in_sizes[0] / Dd;
    int nE = in_sizes[1] / 2;
    const int* src  = ei;
    const int* dstp = ei + nE;

    float *agg, *feat;
    int *deg, *off, *cur, *csr, *bsum;
    __nv_bfloat16 *bhiBase, *bloBase;
    cudaGetSymbolAddress((void**)&agg,  g_agg);
    cudaGetSymbolAddress((void**)&feat, g_feat);
    cudaGetSymbolAddress((void**)&deg,  g_deg);
    cudaGetSymbolAddress((void**)&off,  g_off);
    cudaGetSymbolAddress((void**)&cur,  g_cur);
    cudaGetSymbolAddress((void**)&csr,  g_csr);
    cudaGetSymbolAddress((void**)&bsum, g_bsum);
    cudaGetSymbolAddress((void**)&bhiBase, g_Bhi);
    cudaGetSymbolAddress((void**)&bloBase, g_Blo);

    size_t smem = 512 + (size_t)(2 * MROWS + NP) * KP * sizeof(__nv_bfloat16);
    static bool attrSet = false;
    if (!attrSet) {
        cudaFuncSetAttribute(layer_mma,
                             cudaFuncAttributeMaxDynamicSharedMemorySize, (int)smem);
        attrSet = true;
    }

    // Weight prep (bf16 hi/lo, padded+transposed)
    prep_kernel<<<(3 * NP * KP + 255) / 256, 256>>>(Wsa, Wsr, Wma, Wmr, Wva, Wvr);

    // CSR build
    int nb = (n + SCAN_B - 1) / SCAN_B;
    cudaMemsetAsync(deg, 0, (size_t)n * sizeof(int));
    hist_kernel<<<(nE + 255) / 256, 256>>>(dstp, deg, nE);
    scanA_kernel<<<nb, SCAN_B>>>(deg, cur, bsum, n);
    scanB_kernel<<<1, 32>>>(bsum, nb);
    scanC_kernel<<<nb, SCAN_B>>>(cur, bsum, deg, off, cur, n);
    scatter_kernel<<<(nE + 255) / 256, 256>>>(src, dstp, cur, csr, nE);

    // Layer 1
    int gatherBlocks = (n + 7) / 8;
    gather_kernel<<<gatherBlocks, 256>>>(x, csr, off, agg, n);

    int rowBlocks = (n + MROWS - 1) / MROWS;
    layer_mma<<<dim3(rowBlocks, 1), NTHREADS, smem>>>(
        agg, x, bhiBase, bloBase, bs_,
        bhiBase, bloBase, bs_, feat, n, 1);

    // Layers 2+3 (shared aggregation over feat)
    gather_kernel<<<gatherBlocks, 256>>>(feat, csr, off, agg, n);

    float* outp = (float*)d_out;
    layer_mma<<<dim3(rowBlocks, 2), NTHREADS, smem>>>(
        agg, feat,
        bhiBase + (size_t)1 * NP * KP, bloBase + (size_t)1 * NP * KP, bm,
        bhiBase + (size_t)2 * NP * KP, bloBase + (size_t)2 * NP * KP, bv,
        outp, n, 0);
}

// round 16
// speedup vs baseline: 1.5114x; 1.1510x over previous
#include <cuda_runtime.h>
#include <cuda_bf16.h>
#include <cuda_fp16.h>
#include <cstdint>

#define NMAX 100000
#define EMAX 1700000
#define Dd 100
#define KDATA 200
#define NP 104            // padded output cols (13 x n8)
#define KP 216            // smem k-stride (conflict-free for ldmatrix)
#define MROWS 64          // rows per CTA
#define NTHREADS 256
#define SCAN_B 1024

__device__ float g_agg[(size_t)NMAX * Dd];
__device__ float g_feat[(size_t)NMAX * Dd];
__device__ int   g_deg[NMAX];
__device__ int   g_off[NMAX + 1];
__device__ int   g_cur[NMAX];
__device__ int   g_csr[EMAX];
__device__ int   g_bsum[(NMAX + SCAN_B - 1) / SCAN_B];
__device__ __half g_B[3][NP * KP];   // [set][n*KP + k], k-contiguous, single fp16

// ---------------- CSR build: histogram -> scan -> scatter ----------------

__global__ void hist_kernel(const int* __restrict__ dst, int* deg, int nE) {
    int e = blockIdx.x * blockDim.x + threadIdx.x;
    if (e < nE) atomicAdd(deg + __ldg(dst + e), 1);
}

__global__ void scanA_kernel(const int* __restrict__ deg, int* scanOut,
                             int* bsum, int n) {
    __shared__ int sm[SCAN_B];
    int i = blockIdx.x * SCAN_B + threadIdx.x;
    int v = (i < n) ? deg[i] : 0;
    sm[threadIdx.x] = v;
    __syncthreads();
    for (int o = 1; o < SCAN_B; o <<= 1) {
        int t = (threadIdx.x >= o) ? sm[threadIdx.x - o] : 0;
        __syncthreads();
        sm[threadIdx.x] += t;
        __syncthreads();
    }
    if (i < n) scanOut[i] = sm[threadIdx.x];
    if (threadIdx.x == SCAN_B - 1) bsum[blockIdx.x] = sm[SCAN_B - 1];
}

__global__ void scanB_kernel(int* bsum, int nb) {
    int lane = threadIdx.x;
    int carry = 0;
    for (int base = 0; base < nb; base += 32) {
        int i = base + lane;
        int orig = (i < nb) ? bsum[i] : 0;
        int v = orig;
        #pragma unroll
        for (int o = 1; o < 32; o <<= 1) {
            int t = __shfl_up_sync(0xffffffffu, v, o);
            if (lane >= o) v += t;
        }
        if (i < nb) bsum[i] = carry + (v - orig);
        carry += __shfl_sync(0xffffffffu, v, 31);
    }
}

__global__ void scanC_kernel(const int* __restrict__ scanIn,
                             const int* __restrict__ bsum,
                             const int* __restrict__ deg,
                             int* off, int* cur, int n) {
    int i = blockIdx.x * SCAN_B + threadIdx.x;
    if (i < n) {
        int incl = scanIn[i] + bsum[blockIdx.x];
        off[i + 1] = incl;
        cur[i] = incl - deg[i];
    }
    if (i == 0) off[0] = 0;
}

__global__ void scatter_kernel(const int* __restrict__ src,
                               const int* __restrict__ dst,
                               int* cur, int* csr, int nE) {
    int e = blockIdx.x * blockDim.x + threadIdx.x;
    if (e >= nE) return;
    int pos = atomicAdd(cur + __ldg(dst + e), 1);
    csr[pos] = __ldg(src + e);
}

// ---------------- Gather aggregation: mean of neighbor rows ----------------

__global__ void gather_kernel(const float* __restrict__ xin,
                              const int* __restrict__ csr,
                              const int* __restrict__ off,
                              float* __restrict__ aggOut, int n)
{
    int node = blockIdx.x * 8 + (threadIdx.x >> 5);
    int lane = threadIdx.x & 31;
    if (node >= n) return;
    int s0 = __ldg(off + node), s1 = __ldg(off + node + 1);
    float4 acc = make_float4(0.f, 0.f, 0.f, 0.f);
    int j = s0;
    int idx = (j < s1) ? __ldg(csr + j) : 0;
    while (j < s1) {
        int nidx = (j + 1 < s1) ? __ldg(csr + j + 1) : 0;
        if (lane < 25) {
            float4 v = __ldg(reinterpret_cast<const float4*>(
                    xin + (size_t)idx * Dd) + lane);
            acc.x += v.x; acc.y += v.y; acc.z += v.z; acc.w += v.w;
        }
        idx = nidx;
        j++;
    }
    if (lane < 25) {
        float inv = (s1 > s0) ? 1.0f / (float)(s1 - s0) : 0.f;
        acc.x *= inv; acc.y *= inv; acc.z *= inv; acc.w *= inv;
        reinterpret_cast<float4*>(aggOut + (size_t)node * Dd)[lane] = acc;
    }
}

// ---------------- Weight prep: fp32 W -> padded, transposed fp16 ----------------
__global__ void prep_kernel(const float* __restrict__ Wsa, const float* __restrict__ Wsr,
                            const float* __restrict__ Wma, const float* __restrict__ Wmr,
                            const float* __restrict__ Wva, const float* __restrict__ Wvr)
{
    int i = blockIdx.x * blockDim.x + threadIdx.x;
    if (i >= 3 * NP * KP) return;
    int s = i / (NP * KP);
    int rem = i - s * (NP * KP);
    int nIdx = rem / KP;
    int k = rem - nIdx * KP;
    const float* Wa = (s == 0) ? Wsa : (s == 1) ? Wma : Wva;
    const float* Wr = (s == 0) ? Wsr : (s == 1) ? Wmr : Wvr;
    float v = 0.f;
    if (nIdx < Dd && k < KDATA)
        v = (k < Dd) ? __ldg(Wa + k * Dd + nIdx) : __ldg(Wr + (k - Dd) * Dd + nIdx);
    g_B[s][rem] = __float2half_rn(v);
}

// ---------------- MMA pass: 2-term fp16 split (Ahi + Alo) vs single B ----------------
// One warp computes its 16-row tile x n-tiles [NTBASE, NTBASE+NTC).
// B fragments are loaded once per k-step and reused for both A terms.
template<int NTBASE, int NTC>
__device__ __forceinline__ void mma_pass(
    const __half* __restrict__ Ahi, const __half* __restrict__ Alo,
    const __half* __restrict__ Bbuf, float (*acc)[4],
    int arow, int akoff, int brow, int bkoff)
{
    #pragma unroll 1
    for (int ks = 0; ks < 13; ks++) {
        int k0 = ks * 16;
        uint32_t ah[4], al[4];
        {
            uint32_t addr = (uint32_t)__cvta_generic_to_shared(
                Ahi + arow * KP + k0 + akoff);
            asm volatile(
                "ldmatrix.sync.aligned.m8n8.x4.shared.b16 {%0,%1,%2,%3}, [%4];"
                : "=r"(ah[0]), "=r"(ah[1]), "=r"(ah[2]), "=r"(ah[3]) : "r"(addr));
        }
        {
            uint32_t addr = (uint32_t)__cvta_generic_to_shared(
                Alo + arow * KP + k0 + akoff);
            asm volatile(
                "ldmatrix.sync.aligned.m8n8.x4.shared.b16 {%0,%1,%2,%3}, [%4];"
                : "=r"(al[0]), "=r"(al[1]), "=r"(al[2]), "=r"(al[3]) : "r"(addr));
        }
        uint32_t bf[NTC][2];
        #pragma unroll
        for (int t = 0; t < NTC; t++) {
            uint32_t baddr = (uint32_t)__cvta_generic_to_shared(
                Bbuf + ((NTBASE + t) * 8 + brow) * KP + k0 + bkoff);
            asm volatile(
                "ldmatrix.sync.aligned.m8n8.x2.shared.b16 {%0,%1}, [%2];"
                : "=r"(bf[t][0]), "=r"(bf[t][1]) : "r"(baddr));
        }
        #pragma unroll
        for (int t = 0; t < NTC; t++)
            asm volatile(
                "mma.sync.aligned.m16n8k16.row.col.f32.f16.f16.f32 "
                "{%0,%1,%2,%3}, {%4,%5,%6,%7}, {%8,%9}, {%0,%1,%2,%3};"
                : "+f"(acc[t][0]), "+f"(acc[t][1]), "+f"(acc[t][2]), "+f"(acc[t][3])
                : "r"(ah[0]), "r"(ah[1]), "r"(ah[2]), "r"(ah[3]),
                  "r"(bf[t][0]), "r"(bf[t][1]));
        #pragma unroll
        for (int t = 0; t < NTC; t++)
            asm volatile(
                "mma.sync.aligned.m16n8k16.row.col.f32.f16.f16.f32 "
                "{%0,%1,%2,%3}, {%4,%5,%6,%7}, {%8,%9}, {%0,%1,%2,%3};"
                : "+f"(acc[t][0]), "+f"(acc[t][1]), "+f"(acc[t][2]), "+f"(acc[t][3])
                : "r"(al[0]), "r"(al[1]), "r"(al[2]), "r"(al[3]),
                  "r"(bf[t][0]), "r"(bf[t][1]));
    }
}

// ---------------- Tensor-core layer: 64-row CTAs, 2 CTAs/SM, single B ----------------
// Warps: (wid&3) = row tile (16 rows), (wid>>2) = col group (nt 0..6 / 7..12).
__global__ void __launch_bounds__(NTHREADS, 2)
layer_mma(const float* __restrict__ agg, const float* __restrict__ root,
          const __half* __restrict__ B0, const float* __restrict__ bias0,
          const __half* __restrict__ B1, const float* __restrict__ bias1,
          float* __restrict__ out, int n, int doRelu)
{
    extern __shared__ char smraw[];
    float* sbias = reinterpret_cast<float*>(smraw);                    // 128 floats
    __half* Ahi = reinterpret_cast<__half*>(smraw + 512);
    __half* Alo = Ahi + MROWS * KP;
    __half* Bbuf = Alo + MROWS * KP;

    const __half* gB = blockIdx.y ? B1 : B0;
    const float* gb = blockIdx.y ? bias1 : bias0;
    out += (size_t)blockIdx.y * n * Dd;

    const int tid = threadIdx.x;
    const int base = blockIdx.x * MROWS;

    // Stage B (fp16, already padded/transposed)
    {
        const float4* sh = reinterpret_cast<const float4*>(gB);
        float4* dh = reinterpret_cast<float4*>(Bbuf);
        for (int i = tid; i < (NP * KP) / 8; i += NTHREADS) dh[i] = __ldg(sh + i);
    }
    if (tid < NP) sbias[tid] = (tid < Dd) ? __ldg(gb + tid) : 0.f;

    // Stage A hi/lo (fp16 split): MROWS rows x 50 float4 chunks.
    for (int idx = tid; idx < MROWS * 50; idx += NTHREADS) {
        int r = idx / 50, q = idx - r * 50;
        int node = base + r;
        float4 v = make_float4(0.f, 0.f, 0.f, 0.f);
        if (node < n)
            v = (q < 25) ? __ldg(reinterpret_cast<const float4*>(
                                 agg + (size_t)node * Dd) + q)
                         : __ldg(reinterpret_cast<const float4*>(
                                 root + (size_t)node * Dd) + (q - 25));
        int kb = (q < 25) ? q * 4 : 100 + (q - 25) * 4;
        __half2 h01 = __floats2half2_rn(v.x, v.y);
        __half2 h23 = __floats2half2_rn(v.z, v.w);
        float2 f01 = __half22float2(h01);
        float2 f23 = __half22float2(h23);
        __half2 l01 = __floats2half2_rn(v.x - f01.x, v.y - f01.y);
        __half2 l23 = __floats2half2_rn(v.z - f23.x, v.w - f23.y);
        uint32_t* dh = reinterpret_cast<uint32_t*>(Ahi + r * KP + kb);
        uint32_t* dl = reinterpret_cast<uint32_t*>(Alo + r * KP + kb);
        dh[0] = *reinterpret_cast<uint32_t*>(&h01);
        dh[1] = *reinterpret_cast<uint32_t*>(&h23);
        dl[0] = *reinterpret_cast<uint32_t*>(&l01);
        dl[1] = *reinterpret_cast<uint32_t*>(&l23);
    }
    // Zero A pad cols k=200..207.
    for (int i = tid; i < MROWS * 4; i += NTHREADS) {
        int r = i >> 2, c = i & 3;
        reinterpret_cast<uint32_t*>(Ahi)[r * (KP / 2) + 100 + c] = 0u;
        reinterpret_cast<uint32_t*>(Alo)[r * (KP / 2) + 100 + c] = 0u;
    }
    __syncthreads();

    const int lane = tid & 31;
    const int wid = tid >> 5;
    const int rowTile = wid & 3;
    const int colGrp = wid >> 2;

    const int arow = rowTile * 16 + (lane & 15);
    const int akoff = (lane >> 4) << 3;
    const int brow = lane & 7;
    const int bkoff = ((lane >> 3) & 1) << 3;

    float acc[7][4];
    #pragma unroll
    for (int t = 0; t < 7; t++)
        acc[t][0] = acc[t][1] = acc[t][2] = acc[t][3] = 0.f;

    if (colGrp == 0)
        mma_pass<0, 7>(Ahi, Alo, Bbuf, acc, arow, akoff, brow, bkoff);
    else
        mma_pass<7, 6>(Ahi, Alo, Bbuf, acc, arow, akoff, brow, bkoff);

    // Epilogue: bias (+ReLU), store.
    const int ntBase = colGrp ? 7 : 0;
    const int ntCnt = colGrp ? 6 : 7;
    int row0 = base + rowTile * 16 + (lane >> 2);
    int row1 = row0 + 8;
    #pragma unroll
    for (int t = 0; t < 7; t++) {
        if (t >= ntCnt) break;
        int col0 = (ntBase + t) * 8 + ((lane & 3) << 1);
        if (col0 >= Dd) continue;
        float bv0 = sbias[col0], bv1 = sbias[col0 + 1];
        float v00 = acc[t][0] + bv0, v01 = acc[t][1] + bv1;
        float v10 = acc[t][2] + bv0, v11 = acc[t][3] + bv1;
        if (doRelu) {
            v00 = fmaxf(v00, 0.f); v01 = fmaxf(v01, 0.f);
            v10 = fmaxf(v10, 0.f); v11 = fmaxf(v11, 0.f);
        }
        if (row0 < n)
            *reinterpret_cast<float2*>(out + (size_t)row0 * Dd + col0) =
                make_float2(v00, v01);
        if (row1 < n)
            *reinterpret_cast<float2*>(out + (size_t)row1 * Dd + col0) =
                make_float2(v10, v11);
    }
}

extern "C" void kernel_launch(void* const* d_in, const int* in_sizes, int n_in,
                              void* d_out, int out_size)
{
    const float* x   = (const float*)d_in[0];
    const int*   ei  = (const int*)d_in[1];
    const float* Wsa = (const float*)d_in[3];
    const float* Wsr = (const float*)d_in[4];
    const float* bs_ = (const float*)d_in[5];
    const float* Wma = (const float*)d_in[6];
    const float* Wmr = (const float*)d_in[7];
    const float* bm  = (const float*)d_in[8];
    const float* Wva = (const float*)d_in[9];
    const float* Wvr = (const float*)d_in[10];
    const float* bv  = (const float*)d_in[11];

    int n  = in_sizes[0] / Dd;
    int nE = in_sizes[1] / 2;
    const int* src  = ei;
    const int* dstp = ei + nE;

    float *agg, *feat;
    int *deg, *off, *cur, *csr, *bsum;
    __half *bBase;
    cudaGetSymbolAddress((void**)&agg,  g_agg);
    cudaGetSymbolAddress((void**)&feat, g_feat);
    cudaGetSymbolAddress((void**)&deg,  g_deg);
    cudaGetSymbolAddress((void**)&off,  g_off);
    cudaGetSymbolAddress((void**)&cur,  g_cur);
    cudaGetSymbolAddress((void**)&csr,  g_csr);
    cudaGetSymbolAddress((void**)&bsum, g_bsum);
    cudaGetSymbolAddress((void**)&bBase, g_B);

    size_t smem = 512 + (size_t)(2 * MROWS + NP) * KP * sizeof(__half);
    static bool attrSet = false;
    if (!attrSet) {
        cudaFuncSetAttribute(layer_mma,
                             cudaFuncAttributeMaxDynamicSharedMemorySize, (int)smem);
        attrSet = true;
    }

    // Weight prep (fp16, padded+transposed)
    prep_kernel<<<(3 * NP * KP + 255) / 256, 256>>>(Wsa, Wsr, Wma, Wmr, Wva, Wvr);

    // CSR build
    int nb = (n + SCAN_B - 1) / SCAN_B;
    cudaMemsetAsync(deg, 0, (size_t)n * sizeof(int));
    hist_kernel<<<(nE + 255) / 256, 256>>>(dstp, deg, nE);
    scanA_kernel<<<nb, SCAN_B>>>(deg, cur, bsum, n);
    scanB_kernel<<<1, 32>>>(bsum, nb);
    scanC_kernel<<<nb, SCAN_B>>>(cur, bsum, deg, off, cur, n);
    scatter_kernel<<<(nE + 255) / 256, 256>>>(src, dstp, cur, csr, nE);

    // Layer 1
    int gatherBlocks = (n + 7) / 8;
    gather_kernel<<<gatherBlocks, 256>>>(x, csr, off, agg, n);

    int rowBlocks = (n + MROWS - 1) / MROWS;
    layer_mma<<<dim3(rowBlocks, 1), NTHREADS, smem>>>(
        agg, x, bBase, bs_, bBase, bs_, feat, n, 1);

    // Layers 2+3 (shared aggregation over feat)
    gather_kernel<<<gatherBlocks, 256>>>(feat, csr, off, agg, n);

    float* outp = (float*)d_out;
    layer_mma<<<dim3(rowBlocks, 2), NTHREADS, smem>>>(
        agg, feat,
        bBase + (size_t)1 * NP * KP, bm,
        bBase + (size_t)2 * NP * KP, bv,
        outp, n, 0);
}

// round 17
// speedup vs baseline: 1.6051x; 1.0619x over previous
#include <cuda_runtime.h>
#include <cuda_fp16.h>
#include <cstdint>

#define NMAX 100000
#define EMAX 1700000
#define Dd 100
#define DH 104            // padded fp16 feature row (13 x uint4)
#define NP 104            // padded output cols (13 x n8)
#define KP 216            // smem k-stride; K layout: [agg 0..99 | 0 | root 104..207]
#define MROWS 64          // rows per CTA
#define NTHREADS 256
#define SCAN_B 1024

__device__ float  g_agg[(size_t)NMAX * Dd];
__device__ __half g_xh[(size_t)NMAX * DH];
__device__ __half g_featH[(size_t)NMAX * DH];   // pads 100..103 never written -> stay 0
__device__ int    g_deg[NMAX];
__device__ int    g_off[NMAX + 1];
__device__ int    g_cur[NMAX];
__device__ int    g_csr[EMAX];
__device__ int    g_bsum[(NMAX + SCAN_B - 1) / SCAN_B];
__device__ __half g_B[3][NP * KP];   // [set][n*KP + k], k-contiguous fp16

// ---------------- CSR build: histogram -> scan -> scatter ----------------

__global__ void hist_kernel(const int* __restrict__ dst, int* deg, int nE) {
    int e = blockIdx.x * blockDim.x + threadIdx.x;
    if (e < nE) atomicAdd(deg + __ldg(dst + e), 1);
}

__global__ void scanA_kernel(const int* __restrict__ deg, int* scanOut,
                             int* bsum, int n) {
    __shared__ int sm[SCAN_B];
    int i = blockIdx.x * SCAN_B + threadIdx.x;
    int v = (i < n) ? deg[i] : 0;
    sm[threadIdx.x] = v;
    __syncthreads();
    for (int o = 1; o < SCAN_B; o <<= 1) {
        int t = (threadIdx.x >= o) ? sm[threadIdx.x - o] : 0;
        __syncthreads();
        sm[threadIdx.x] += t;
        __syncthreads();
    }
    if (i < n) scanOut[i] = sm[threadIdx.x];
    if (threadIdx.x == SCAN_B - 1) bsum[blockIdx.x] = sm[SCAN_B - 1];
}

__global__ void scanB_kernel(int* bsum, int nb) {
    int lane = threadIdx.x;
    int carry = 0;
    for (int base = 0; base < nb; base += 32) {
        int i = base + lane;
        int orig = (i < nb) ? bsum[i] : 0;
        int v = orig;
        #pragma unroll
        for (int o = 1; o < 32; o <<= 1) {
            int t = __shfl_up_sync(0xffffffffu, v, o);
            if (lane >= o) v += t;
        }
        if (i < nb) bsum[i] = carry + (v - orig);
        carry += __shfl_sync(0xffffffffu, v, 31);
    }
}

__global__ void scanC_kernel(const int* __restrict__ scanIn,
                             const int* __restrict__ bsum,
                             const int* __restrict__ deg,
                             int* off, int* cur, int n) {
    int i = blockIdx.x * SCAN_B + threadIdx.x;
    if (i < n) {
        int incl = scanIn[i] + bsum[blockIdx.x];
        off[i + 1] = incl;
        cur[i] = incl - deg[i];
    }
    if (i == 0) off[0] = 0;
}

__global__ void scatter_kernel(const int* __restrict__ src,
                               const int* __restrict__ dst,
                               int* cur, int* csr, int nE) {
    int e = blockIdx.x * blockDim.x + threadIdx.x;
    if (e >= nE) return;
    int pos = atomicAdd(cur + __ldg(dst + e), 1);
    csr[pos] = __ldg(src + e);
}

// ---------------- x -> padded fp16 ----------------
__global__ void x2h_kernel(const float* __restrict__ x, __half* __restrict__ xh, int n) {
    int i = blockIdx.x * blockDim.x + threadIdx.x;   // one half2 (2 cols)
    if (i >= n * (DH / 2)) return;
    int r = i / (DH / 2);
    int c0 = (i - r * (DH / 2)) * 2;
    float a = (c0 < Dd)     ? __ldg(x + (size_t)r * Dd + c0)     : 0.f;
    float b = (c0 + 1 < Dd) ? __ldg(x + (size_t)r * Dd + c0 + 1) : 0.f;
    reinterpret_cast<__half2*>(xh)[i] = __floats2half2_rn(a, b);
}

// ---------------- Gather aggregation (fp16 rows, fp32 accumulate) ----------------
// One warp per node; lanes 0..12 each own one uint4 = 8 halfs of the 104-col row.
__global__ void gather_kernel(const __half* __restrict__ xh,
                              const int* __restrict__ csr,
                              const int* __restrict__ off,
                              float* __restrict__ aggOut, int n)
{
    int node = blockIdx.x * 8 + (threadIdx.x >> 5);
    int lane = threadIdx.x & 31;
    if (node >= n) return;
    int s0 = __ldg(off + node), s1 = __ldg(off + node + 1);

    float acc[8];
    #pragma unroll
    for (int p = 0; p < 8; p++) acc[p] = 0.f;

    int j = s0;
    int idx = (j < s1) ? __ldg(csr + j) : 0;
    while (j < s1) {
        int nidx = (j + 1 < s1) ? __ldg(csr + j + 1) : 0;
        if (lane < 13) {
            uint4 v = __ldg(reinterpret_cast<const uint4*>(
                    xh + (size_t)idx * DH) + lane);
            const __half2* h = reinterpret_cast<const __half2*>(&v);
            #pragma unroll
            for (int p = 0; p < 4; p++) {
                float2 f = __half22float2(h[p]);
                acc[2 * p]     += f.x;
                acc[2 * p + 1] += f.y;
            }
        }
        idx = nidx;
        j++;
    }
    if (lane < 13) {
        float inv = (s1 > s0) ? 1.0f / (float)(s1 - s0) : 0.f;
        #pragma unroll
        for (int p = 0; p < 8; p++) acc[p] *= inv;
        int c0 = lane * 8;                       // cols c0..c0+7 (lane 12: keep 96..99)
        float* orow = aggOut + (size_t)node * Dd;
        *reinterpret_cast<float4*>(orow + c0) =
            make_float4(acc[0], acc[1], acc[2], acc[3]);
        if (c0 + 4 < Dd)
            *reinterpret_cast<float4*>(orow + c0 + 4) =
                make_float4(acc[4], acc[5], acc[6], acc[7]);
    }
}

// ---------------- Weight prep: K layout [Wa 0..99 | 0 | Wr 104..203 | 0] ----------------
__global__ void prep_kernel(const float* __restrict__ Wsa, const float* __restrict__ Wsr,
                            const float* __restrict__ Wma, const float* __restrict__ Wmr,
                            const float* __restrict__ Wva, const float* __restrict__ Wvr)
{
    int i = blockIdx.x * blockDim.x + threadIdx.x;
    if (i >= 3 * NP * KP) return;
    int s = i / (NP * KP);
    int rem = i - s * (NP * KP);
    int nIdx = rem / KP;
    int k = rem - nIdx * KP;
    const float* Wa = (s == 0) ? Wsa : (s == 1) ? Wma : Wva;
    const float* Wr = (s == 0) ? Wsr : (s == 1) ? Wmr : Wvr;
    float v = 0.f;
    if (nIdx < Dd) {
        if (k < Dd) v = __ldg(Wa + k * Dd + nIdx);
        else if (k >= 104 && k < 204) v = __ldg(Wr + (k - 104) * Dd + nIdx);
    }
    g_B[s][rem] = __float2half_rn(v);
}

// ---------------- MMA pass: hi full 13 ksteps, lo only 7 (root-lo is zero) ----------------
template<int NTBASE, int NTC>
__device__ __forceinline__ void mma_pass(
    const __half* __restrict__ Ahi, const __half* __restrict__ Alo,
    const __half* __restrict__ Bbuf, float (*acc)[4],
    int arow, int akoff, int brow, int bkoff)
{
    #pragma unroll 1
    for (int ks = 0; ks < 13; ks++) {
        int k0 = ks * 16;
        uint32_t ah[4], al[4];
        {
            uint32_t addr = (uint32_t)__cvta_generic_to_shared(
                Ahi + arow * KP + k0 + akoff);
            asm volatile(
                "ldmatrix.sync.aligned.m8n8.x4.shared.b16 {%0,%1,%2,%3}, [%4];"
                : "=r"(ah[0]), "=r"(ah[1]), "=r"(ah[2]), "=r"(ah[3]) : "r"(addr));
        }
        uint32_t bf[NTC][2];
        #pragma unroll
        for (int t = 0; t < NTC; t++) {
            uint32_t baddr = (uint32_t)__cvta_generic_to_shared(
                Bbuf + ((NTBASE + t) * 8 + brow) * KP + k0 + bkoff);
            asm volatile(
                "ldmatrix.sync.aligned.m8n8.x2.shared.b16 {%0,%1}, [%2];"
                : "=r"(bf[t][0]), "=r"(bf[t][1]) : "r"(baddr));
        }
        #pragma unroll
        for (int t = 0; t < NTC; t++)
            asm volatile(
                "mma.sync.aligned.m16n8k16.row.col.f32.f16.f16.f32 "
                "{%0,%1,%2,%3}, {%4,%5,%6,%7}, {%8,%9}, {%0,%1,%2,%3};"
                : "+f"(acc[t][0]), "+f"(acc[t][1]), "+f"(acc[t][2]), "+f"(acc[t][3])
                : "r"(ah[0]), "r"(ah[1]), "r"(ah[2]), "r"(ah[3]),
                  "r"(bf[t][0]), "r"(bf[t][1]));
        if (ks < 7) {
            uint32_t addr = (uint32_t)__cvta_generic_to_shared(
                Alo + arow * KP + k0 + akoff);
            asm volatile(
                "ldmatrix.sync.aligned.m8n8.x4.shared.b16 {%0,%1,%2,%3}, [%4];"
                : "=r"(al[0]), "=r"(al[1]), "=r"(al[2]), "=r"(al[3]) : "r"(addr));
            #pragma unroll
            for (int t = 0; t < NTC; t++)
                asm volatile(
                    "mma.sync.aligned.m16n8k16.row.col.f32.f16.f16.f32 "
                    "{%0,%1,%2,%3}, {%4,%5,%6,%7}, {%8,%9}, {%0,%1,%2,%3};"
                    : "+f"(acc[t][0]), "+f"(acc[t][1]), "+f"(acc[t][2]), "+f"(acc[t][3])
                    : "r"(al[0]), "r"(al[1]), "r"(al[2]), "r"(al[3]),
                      "r"(bf[t][0]), "r"(bf[t][1]));
        }
    }
}

// ---------------- Tensor-core layer ----------------
// A = [agg(fp32, hi/lo split) k0..99 | rootH(fp16, exact) k104..207].
// outH != null (layer 1): write fp16 featH only. outH == null: write fp32 out.
__global__ void __launch_bounds__(NTHREADS, 2)
layer_mma(const float* __restrict__ agg, const __half* __restrict__ rootH,
          const __half* __restrict__ B0, const float* __restrict__ bias0,
          const __half* __restrict__ B1, const float* __restrict__ bias1,
          float* __restrict__ out, __half* __restrict__ outH, int n, int doRelu)
{
    extern __shared__ char smraw[];
    float* sbias = reinterpret_cast<float*>(smraw);
    __half* Ahi = reinterpret_cast<__half*>(smraw + 512);
    __half* Alo = Ahi + MROWS * KP;
    __half* Bbuf = Alo + MROWS * KP;

    const __half* gB = blockIdx.y ? B1 : B0;
    const float* gb = blockIdx.y ? bias1 : bias0;
    if (out) out += (size_t)blockIdx.y * n * Dd;

    const int tid = threadIdx.x;
    const int base = blockIdx.x * MROWS;

    // Stage B
    {
        const float4* sh = reinterpret_cast<const float4*>(gB);
        float4* dh = reinterpret_cast<float4*>(Bbuf);
        for (int i = tid; i < (NP * KP) / 8; i += NTHREADS) dh[i] = __ldg(sh + i);
    }
    if (tid < NP) sbias[tid] = (tid < Dd) ? __ldg(gb + tid) : 0.f;

    // Stage agg (fp32 -> fp16 hi/lo) at k 0..99
    for (int idx = tid; idx < MROWS * 25; idx += NTHREADS) {
        int r = idx / 25, q = idx - r * 25;
        int node = base + r;
        float4 v = make_float4(0.f, 0.f, 0.f, 0.f);
        if (node < n)
            v = __ldg(reinterpret_cast<const float4*>(agg + (size_t)node * Dd) + q);
        __half2 h01 = __floats2half2_rn(v.x, v.y);
        __half2 h23 = __floats2half2_rn(v.z, v.w);
        float2 f01 = __half22float2(h01);
        float2 f23 = __half22float2(h23);
        __half2 l01 = __floats2half2_rn(v.x - f01.x, v.y - f01.y);
        __half2 l23 = __floats2half2_rn(v.z - f23.x, v.w - f23.y);
        uint32_t* dh = reinterpret_cast<uint32_t*>(Ahi + r * KP + 4 * q);
        uint32_t* dl = reinterpret_cast<uint32_t*>(Alo + r * KP + 4 * q);
        dh[0] = *reinterpret_cast<uint32_t*>(&h01);
        dh[1] = *reinterpret_cast<uint32_t*>(&h23);
        dl[0] = *reinterpret_cast<uint32_t*>(&l01);
        dl[1] = *reinterpret_cast<uint32_t*>(&l23);
    }
    // Stage rootH (fp16 copy) at k 104..207 (pads 204..207 come from rootH cols 100..103 = 0)
    for (int idx = tid; idx < MROWS * 13; idx += NTHREADS) {
        int r = idx / 13, q = idx - r * 13;
        int node = base + r;
        uint4 v = make_uint4(0u, 0u, 0u, 0u);
        if (node < n)
            v = __ldg(reinterpret_cast<const uint4*>(rootH + (size_t)node * DH) + q);
        *reinterpret_cast<uint4*>(Ahi + r * KP + 104 + 8 * q) = v;
    }
    // Zero pads: Ahi k100..103 (2 u32/row), Alo k100..115 (8 u32/row; lo reads stop at k111)
    for (int i = tid; i < MROWS * 2; i += NTHREADS) {
        int r = i >> 1, c = i & 1;
        reinterpret_cast<uint32_t*>(Ahi)[r * (KP / 2) + 50 + c] = 0u;
    }
    for (int i = tid; i < MROWS * 8; i += NTHREADS) {
        int r = i >> 3, c = i & 7;
        reinterpret_cast<uint32_t*>(Alo)[r * (KP / 2) + 50 + c] = 0u;
    }
    __syncthreads();

    const int lane = tid & 31;
    const int wid = tid >> 5;
    const int rowTile = wid & 3;
    const int colGrp = wid >> 2;

    const int arow = rowTile * 16 + (lane & 15);
    const int akoff = (lane >> 4) << 3;
    const int brow = lane & 7;
    const int bkoff = ((lane >> 3) & 1) << 3;

    float acc[7][4];
    #pragma unroll
    for (int t = 0; t < 7; t++)
        acc[t][0] = acc[t][1] = acc[t][2] = acc[t][3] = 0.f;

    if (colGrp == 0)
        mma_pass<0, 7>(Ahi, Alo, Bbuf, acc, arow, akoff, brow, bkoff);
    else
        mma_pass<7, 6>(Ahi, Alo, Bbuf, acc, arow, akoff, brow, bkoff);

    // Epilogue
    const int ntBase = colGrp ? 7 : 0;
    const int ntCnt = colGrp ? 6 : 7;
    int row0 = base + rowTile * 16 + (lane >> 2);
    int row1 = row0 + 8;
    #pragma unroll
    for (int t = 0; t < 7; t++) {
        if (t >= ntCnt) break;
        int col0 = (ntBase + t) * 8 + ((lane & 3) << 1);
        if (col0 >= Dd) continue;
        float bv0 = sbias[col0], bv1 = sbias[col0 + 1];
        float v00 = acc[t][0] + bv0, v01 = acc[t][1] + bv1;
        float v10 = acc[t][2] + bv0, v11 = acc[t][3] + bv1;
        if (doRelu) {
            v00 = fmaxf(v00, 0.f); v01 = fmaxf(v01, 0.f);
            v10 = fmaxf(v10, 0.f); v11 = fmaxf(v11, 0.f);
        }
        if (outH) {
            if (row0 < n)
                *reinterpret_cast<__half2*>(outH + (size_t)row0 * DH + col0) =
                    __floats2half2_rn(v00, v01);
            if (row1 < n)
                *reinterpret_cast<__half2*>(outH + (size_t)row1 * DH + col0) =
                    __floats2half2_rn(v10, v11);
        } else {
            if (row0 < n)
                *reinterpret_cast<float2*>(out + (size_t)row0 * Dd + col0) =
                    make_float2(v00, v01);
            if (row1 < n)
                *reinterpret_cast<float2*>(out + (size_t)row1 * Dd + col0) =
                    make_float2(v10, v11);
        }
    }
}

extern "C" void kernel_launch(void* const* d_in, const int* in_sizes, int n_in,
                              void* d_out, int out_size)
{
    const float* x   = (const float*)d_in[0];
    const int*   ei  = (const int*)d_in[1];
    const float* Wsa = (const float*)d_in[3];
    const float* Wsr = (const float*)d_in[4];
    const float* bs_ = (const float*)d_in[5];
    const float* Wma = (const float*)d_in[6];
    const float* Wmr = (const float*)d_in[7];
    const float* bm  = (const float*)d_in[8];
    const float* Wva = (const float*)d_in[9];
    const float* Wvr = (const float*)d_in[10];
    const float* bv  = (const float*)d_in[11];

    int n  = in_sizes[0] / Dd;
    int nE = in_sizes[1] / 2;
    const int* src  = ei;
    const int* dstp = ei + nE;

    float *agg;
    __half *xh, *featH, *bBase;
    int *deg, *off, *cur, *csr, *bsum;
    cudaGetSymbolAddress((void**)&agg,   g_agg);
    cudaGetSymbolAddress((void**)&xh,    g_xh);
    cudaGetSymbolAddress((void**)&featH, g_featH);
    cudaGetSymbolAddress((void**)&deg,   g_deg);
    cudaGetSymbolAddress((void**)&off,   g_off);
    cudaGetSymbolAddress((void**)&cur,   g_cur);
    cudaGetSymbolAddress((void**)&csr,   g_csr);
    cudaGetSymbolAddress((void**)&bsum,  g_bsum);
    cudaGetSymbolAddress((void**)&bBase, g_B);

    size_t smem = 512 + (size_t)(2 * MROWS + NP) * KP * sizeof(__half);
    static bool attrSet = false;
    if (!attrSet) {
        cudaFuncSetAttribute(layer_mma,
                             cudaFuncAttributeMaxDynamicSharedMemorySize, (int)smem);
        attrSet = true;
    }

    // Weight prep + x -> fp16
    prep_kernel<<<(3 * NP * KP + 255) / 256, 256>>>(Wsa, Wsr, Wma, Wmr, Wva, Wvr);
    x2h_kernel<<<(n * (DH / 2) + 255) / 256, 256>>>(x, xh, n);

    // CSR build
    int nb = (n + SCAN_B - 1) / SCAN_B;
    cudaMemsetAsync(deg, 0, (size_t)n * sizeof(int));
    hist_kernel<<<(nE + 255) / 256, 256>>>(dstp, deg, nE);
    scanA_kernel<<<nb, SCAN_B>>>(deg, cur, bsum, n);
    scanB_kernel<<<1, 32>>>(bsum, nb);
    scanC_kernel<<<nb, SCAN_B>>>(cur, bsum, deg, off, cur, n);
    scatter_kernel<<<(nE + 255) / 256, 256>>>(src, dstp, cur, csr, nE);

    // Layer 1: gather(xh) -> layer -> featH (fp16 only)
    int gatherBlocks = (n + 7) / 8;
    gather_kernel<<<gatherBlocks, 256>>>(xh, csr, off, agg, n);

    int rowBlocks = (n + MROWS - 1) / MROWS;
    layer_mma<<<dim3(rowBlocks, 1), NTHREADS, smem>>>(
        agg, xh, bBase, bs_, bBase, bs_, nullptr, featH, n, 1);

    // Layers 2+3: gather(featH) -> fused mu/var
    gather_kernel<<<gatherBlocks, 256>>>(featH, csr, off, agg, n);

    float* outp = (float*)d_out;
    layer_mma<<<dim3(rowBlocks, 2), NTHREADS, smem>>>(
        agg, featH,
        bBase + (size_t)1 * NP * KP, bm,
        bBase + (size_t)2 * NP * KP, bv,
        outp, nullptr, n, 0);
}